// round 3
// baseline (speedup 1.0000x reference)
#include <cuda_runtime.h>
#include <math_constants.h>

// Problem constants
#define BB 4
#define NN 4096
#define F_IN 64
#define N_PROP 64
#define N_DIM 4
#define N_FILT 128
#define KN 39          // neighbors kept (top-40 minus self)
#define FULL 0xFFFFFFFFu
#define NBBUF 192

// Scratch (allocation-free rule: __device__ globals)
__device__ float g_features[BB*NN*N_PROP];
__device__ float g_coords[BB*NN*N_DIM];
__device__ int   g_nbr_idx[BB*NN*KN];
__device__ float g_nbr_w[BB*NN*KN];

// ---------------------------------------------------------------------------
// K1: features = x@W_flr + b_flr ; coords = x@W_s + b_s
// Block = 16 rows. W in smem (loaded once per block), 4 rows per thread.
// ---------------------------------------------------------------------------
__global__ void __launch_bounds__(256) k_feat(
    const float* __restrict__ x,
    const float* __restrict__ Wf, const float* __restrict__ bf,
    const float* __restrict__ Ws, const float* __restrict__ bs)
{
    __shared__ float Wfs[64*64];
    __shared__ float Wss[64*4];
    __shared__ float xs[16][64];

    int t = threadIdx.x;
    int row0 = blockIdx.x * 16;

    for (int k = t; k < 64*64/4; k += 256) ((float4*)Wfs)[k] = ((const float4*)Wf)[k];
    if (t < 64) ((float4*)Wss)[t] = ((const float4*)Ws)[t];
    for (int k = t; k < 16*64/4; k += 256)
        ((float4*)xs)[k] = ((const float4*)(x + row0 * F_IN))[k];
    __syncthreads();

    int j = t & 63, rg = t >> 6;
    float b0 = bf[j];
    float a0 = b0, a1 = b0, a2 = b0, a3 = b0;
#pragma unroll
    for (int i = 0; i < 64; i++) {
        float wv = Wfs[i * 64 + j];
        a0 = fmaf(xs[rg*4+0][i], wv, a0);
        a1 = fmaf(xs[rg*4+1][i], wv, a1);
        a2 = fmaf(xs[rg*4+2][i], wv, a2);
        a3 = fmaf(xs[rg*4+3][i], wv, a3);
    }
    g_features[(row0 + rg*4 + 0) * N_PROP + j] = a0;
    g_features[(row0 + rg*4 + 1) * N_PROP + j] = a1;
    g_features[(row0 + rg*4 + 2) * N_PROP + j] = a2;
    g_features[(row0 + rg*4 + 3) * N_PROP + j] = a3;

    if (t < 64) {
        int r = t >> 2, c = t & 3;
        float a = bs[c];
#pragma unroll
        for (int i = 0; i < 64; i++)
            a = fmaf(xs[r][i], Wss[i * 4 + c], a);
        g_coords[(row0 + r) * N_DIM + c] = a;
    }
}

// ---------------------------------------------------------------------------
// K2: warp-per-query exact top-39. Single radix pass (10-bit exp+mantissa
// prefix) with warp-aggregated (match_any) histogram atomics, then one
// collect pass with ballot positioning; boundary bin resolved exactly.
// smem: float4 sc[4096] | uint hist[8][1024] | uint2 bbuf[8][NBBUF]
// ---------------------------------------------------------------------------
__device__ __forceinline__ float dist4(float4 q, float4 p) {
    float dx = q.x - p.x, dy = q.y - p.y, dz = q.z - p.z, dw = q.w - p.w;
    return fmaf(dx, dx, fmaf(dy, dy, fmaf(dz, dz, dw * dw)));
}
// transposed hist layout: lane L owns bins [L*32, L*32+32); addr reads conflict-free
__device__ __forceinline__ int haddr(int bin) { return ((bin & 31) << 5) | (bin >> 5); }

__global__ void __launch_bounds__(256, 2) k_knn()
{
    extern __shared__ char smem_raw[];
    float4* sc   = (float4*)smem_raw;                         // 65536
    uint*   hist = (uint*)(smem_raw + 65536);                 // 32768
    uint2*  bbuf = (uint2*)(smem_raw + 65536 + 32768);        // 8*NBBUF*8

    int b = blockIdx.y;
    const float4* cp = (const float4*)(g_coords + b * NN * N_DIM);
    for (int i = threadIdx.x; i < NN; i += blockDim.x) sc[i] = cp[i];
    __syncthreads();

    int w    = threadIdx.x >> 5;
    int lane = threadIdx.x & 31;
    int n    = blockIdx.x * 8 + w;
    float4 q = sc[n];
    uint* h  = hist + w * 1024;
    uint lmask = (1u << lane) - 1u;

    // ---- Pass A: histogram of 10-bit prefixes, warp-aggregated atomics ----
    {
        uint4 z = make_uint4(0, 0, 0, 0);
#pragma unroll
        for (int k = 0; k < 8; k++) ((uint4*)h)[lane * 8 + k] = z;
    }
    __syncwarp();

#pragma unroll 4
    for (int t = 0; t < 128; t++) {
        int j = lane + 32 * t;
        float d = dist4(q, sc[j]);
        uint bin = __float_as_uint(d) >> 21;      // <1024 for d>=0
        if (j == n) bin = 2048;                   // self sentinel
        uint m = __match_any_sync(FULL, bin);
        if (bin < 1024 && lane == (uint)(__ffs(m) - 1))
            atomicAdd(&h[haddr(bin)], __popc(m));
    }
    __syncwarp();

    // lane-local totals + warp scan -> find boundary bin t0
    int local = 0;
#pragma unroll 8
    for (int k = 0; k < 32; k++) local += h[k * 32 + lane];
    int incl = local;
#pragma unroll
    for (int o = 1; o < 32; o <<= 1) {
        int v = __shfl_up_sync(FULL, incl, o);
        if (lane >= o) incl += v;
    }
    int excl = incl - local;

    unsigned ball = __ballot_sync(FULL, excl < KN && KN <= incl);
    int sel = __ffs(ball) - 1;
    int t0 = 0;
    if (lane == sel) {
        int c = excl;
#pragma unroll 8
        for (int k = 0; k < 32; k++) {
            int hc = h[k * 32 + lane];
            if (c + hc >= KN) { t0 = lane * 32 + k; break; }
            c += hc;
        }
    }
    t0 = __shfl_sync(FULL, t0, sel);

    // ---- Collect: prefix<t0 accepted (ballot positions); ==t0 buffered ----
    int base = (b * NN + n) * KN;
    int cbase = 0, bcnt = 0;
#pragma unroll 2
    for (int t = 0; t < 128; t++) {
        int j = lane + 32 * t;
        float d = dist4(q, sc[j]);
        uint key = __float_as_uint(d);
        int  pfx = (int)(key >> 21);
        bool valid = (j != n);
        bool acc = valid && pfx < t0;
        bool bnd = valid && pfx == t0;
        uint ba = __ballot_sync(FULL, acc);
        uint bb = __ballot_sync(FULL, bnd);
        if (acc) {
            int pos = cbase + __popc(ba & lmask);
            g_nbr_idx[base + pos] = j;
            g_nbr_w[base + pos]   = expf(-10.0f * d);
        }
        if (bnd) {
            int bp = bcnt + __popc(bb & lmask);
            if (bp < NBBUF) bbuf[w * NBBUF + bp] = make_uint2(key, (uint)j);
        }
        cbase += __popc(ba);
        bcnt  += __popc(bb);
    }
    __syncwarp();

    // ---- Boundary: exact rank among the == t0 candidates ----
    int need = KN - cbase;
    int M = min(bcnt, NBBUF);
    for (int r0 = 0; r0 < M; r0 += 32) {
        int s = r0 + lane;
        bool act = s < M;
        uint2 e = act ? bbuf[w * NBBUF + s] : make_uint2(0u, 0u);
        int rank = 0;
        if (act) {
            for (int i = 0; i < M; i++) {
                uint2 o = bbuf[w * NBBUF + i];   // broadcast read
                rank += (o.x < e.x) || (o.x == e.x && o.y < e.y);
            }
        }
        bool selp = act && rank < need;
        uint bs_ = __ballot_sync(FULL, selp);
        if (selp) {
            int pos = cbase + __popc(bs_ & lmask);
            g_nbr_idx[base + pos] = (int)e.y;
            g_nbr_w[base + pos]   = expf(-10.0f * __uint_as_float(e.x));
        }
        cbase += __popc(bs_);
    }
}

// ---------------------------------------------------------------------------
// K3: weighted gather -> max/mean -> concat -> @W_out + b_out.
// Warp handles 4 queries: aggregation serial per query, then a 4-row GEMM
// so each W_out float4 load feeds 16 FMAs.
// ---------------------------------------------------------------------------
__global__ void __launch_bounds__(256) k_agg(
    const float* __restrict__ x,
    const float* __restrict__ Wo, const float* __restrict__ bo,
    float* __restrict__ out)
{
    __shared__ float upd[32][192];
    int warp = threadIdx.x >> 5, lane = threadIdx.x & 31;
    int q0 = blockIdx.x * 32 + warp * 4;
    const float inv = 1.0f / 39.0f;

#pragma unroll
    for (int qq = 0; qq < 4; qq++) {
        int r = q0 + qq;
        const float* fb = g_features + (r >> 12) * NN * N_PROP;
        int bk = r * KN;
        float mx0 = -CUDART_INF_F, mx1 = -CUDART_INF_F, s0 = 0.f, s1 = 0.f;
#pragma unroll 8
        for (int k = 0; k < KN; k++) {
            int   jj = __ldg(&g_nbr_idx[bk + k]);
            float wt = __ldg(&g_nbr_w[bk + k]);
            float2 f = ((const float2*)(fb + jj * N_PROP))[lane];
            float v0 = wt * f.x, v1 = wt * f.y;
            mx0 = fmaxf(mx0, v0); mx1 = fmaxf(mx1, v1);
            s0 += v0; s1 += v1;
        }
        float2 xv = ((const float2*)(x + r * F_IN))[lane];
        int ql = warp * 4 + qq;
        upd[ql][2*lane]         = xv.x;
        upd[ql][2*lane + 1]     = xv.y;
        upd[ql][64 + 2*lane]    = mx0;
        upd[ql][64 + 2*lane+1]  = mx1;
        upd[ql][128 + 2*lane]   = s0 * inv;
        upd[ql][128 + 2*lane+1] = s1 * inv;
    }
    __syncwarp();

    float4 bv = ((const float4*)bo)[lane];
    float4 a0 = bv, a1 = bv, a2 = bv, a3 = bv;
    int ql0 = warp * 4;
#pragma unroll 4
    for (int c = 0; c < 192; c++) {
        float4 wv = ((const float4*)(Wo + c * N_FILT))[lane];
        float u0 = upd[ql0 + 0][c];
        float u1 = upd[ql0 + 1][c];
        float u2 = upd[ql0 + 2][c];
        float u3 = upd[ql0 + 3][c];
        a0.x = fmaf(u0, wv.x, a0.x); a0.y = fmaf(u0, wv.y, a0.y);
        a0.z = fmaf(u0, wv.z, a0.z); a0.w = fmaf(u0, wv.w, a0.w);
        a1.x = fmaf(u1, wv.x, a1.x); a1.y = fmaf(u1, wv.y, a1.y);
        a1.z = fmaf(u1, wv.z, a1.z); a1.w = fmaf(u1, wv.w, a1.w);
        a2.x = fmaf(u2, wv.x, a2.x); a2.y = fmaf(u2, wv.y, a2.y);
        a2.z = fmaf(u2, wv.z, a2.z); a2.w = fmaf(u2, wv.w, a2.w);
        a3.x = fmaf(u3, wv.x, a3.x); a3.y = fmaf(u3, wv.y, a3.y);
        a3.z = fmaf(u3, wv.z, a3.z); a3.w = fmaf(u3, wv.w, a3.w);
    }
    ((float4*)(out + (q0 + 0) * N_FILT))[lane] = a0;
    ((float4*)(out + (q0 + 1) * N_FILT))[lane] = a1;
    ((float4*)(out + (q0 + 2) * N_FILT))[lane] = a2;
    ((float4*)(out + (q0 + 3) * N_FILT))[lane] = a3;
}

// ---------------------------------------------------------------------------
extern "C" void kernel_launch(void* const* d_in, const int* in_sizes, int n_in,
                              void* d_out, int out_size)
{
    const float* x  = (const float*)d_in[0];
    const float* Wf = (const float*)d_in[1];
    const float* bf = (const float*)d_in[2];
    const float* Ws = (const float*)d_in[3];
    const float* bs = (const float*)d_in[4];
    const float* Wo = (const float*)d_in[5];
    const float* bo = (const float*)d_in[6];
    float* out = (float*)d_out;

    const int knn_smem = 65536 + 32768 + 8 * NBBUF * 8;   // 110592
    cudaFuncSetAttribute(k_knn, cudaFuncAttributeMaxDynamicSharedMemorySize, knn_smem);

    k_feat<<<BB * NN / 16, 256>>>(x, Wf, bf, Ws, bs);

    dim3 g2(NN / 8, BB);
    k_knn<<<g2, 256, knn_smem>>>();

    k_agg<<<BB * NN / 32, 256>>>(x, Wo, bo, out);
}

// round 5
// speedup vs baseline: 1.3348x; 1.3348x over previous
#include <cuda_runtime.h>
#include <math_constants.h>

// Problem constants
#define BB 4
#define NN 4096
#define F_IN 64
#define N_PROP 64
#define N_DIM 4
#define N_FILT 128
#define KN 39          // neighbors kept (top-40 minus self)
#define FULL 0xFFFFFFFFu
#define NBBUF 192

// Scratch (allocation-free rule: __device__ globals)
__device__ float g_features[BB*NN*N_PROP];
__device__ float g_coords[BB*NN*N_DIM];
__device__ int   g_nbr_idx[BB*NN*KN];
__device__ float g_nbr_w[BB*NN*KN];

// ---------------------------------------------------------------------------
// K1: features = x@W_flr + b_flr ; coords = x@W_s + b_s
// Block = 16 rows. W in smem (loaded once per block), 4 rows per thread.
// ---------------------------------------------------------------------------
__global__ void __launch_bounds__(256) k_feat(
    const float* __restrict__ x,
    const float* __restrict__ Wf, const float* __restrict__ bf,
    const float* __restrict__ Ws, const float* __restrict__ bs)
{
    __shared__ float Wfs[64*64];
    __shared__ float Wss[64*4];
    __shared__ float xs[16][64];

    int t = threadIdx.x;
    int row0 = blockIdx.x * 16;

    for (int k = t; k < 64*64/4; k += 256) ((float4*)Wfs)[k] = ((const float4*)Wf)[k];
    if (t < 64) ((float4*)Wss)[t] = ((const float4*)Ws)[t];
    for (int k = t; k < 16*64/4; k += 256)
        ((float4*)xs)[k] = ((const float4*)(x + row0 * F_IN))[k];
    __syncthreads();

    int j = t & 63, rg = t >> 6;
    float b0 = bf[j];
    float a0 = b0, a1 = b0, a2 = b0, a3 = b0;
#pragma unroll
    for (int i = 0; i < 64; i++) {
        float wv = Wfs[i * 64 + j];
        a0 = fmaf(xs[rg*4+0][i], wv, a0);
        a1 = fmaf(xs[rg*4+1][i], wv, a1);
        a2 = fmaf(xs[rg*4+2][i], wv, a2);
        a3 = fmaf(xs[rg*4+3][i], wv, a3);
    }
    g_features[(row0 + rg*4 + 0) * N_PROP + j] = a0;
    g_features[(row0 + rg*4 + 1) * N_PROP + j] = a1;
    g_features[(row0 + rg*4 + 2) * N_PROP + j] = a2;
    g_features[(row0 + rg*4 + 3) * N_PROP + j] = a3;

    if (t < 64) {
        int r = t >> 2, c = t & 3;
        float a = bs[c];
#pragma unroll
        for (int i = 0; i < 64; i++)
            a = fmaf(xs[r][i], Wss[i * 4 + c], a);
        g_coords[(row0 + r) * N_DIM + c] = a;
    }
}

// ---------------------------------------------------------------------------
// K2: warp-per-query exact top-39.
// Pass A: 64-bin lane-private byte histogram (no atomics, no match),
//         2 ping-pong copies to break the RMW dependency chain.
// Reduce: dp4a byte-column sums + warp scan -> boundary bin t0.
// Pass C: collect with ballot positioning; ==t0 buffered, exact-rank fixup.
// smem: float4 sc[4096] (64K) | u8 hist[8][2][64][32] (32K) | uint2 bbuf[8][192] (12K)
// ---------------------------------------------------------------------------
__device__ __forceinline__ float dist4(float4 q, float4 p) {
    float dx = q.x - p.x, dy = q.y - p.y, dz = q.z - p.z, dw = q.w - p.w;
    return fmaf(dx, dx, fmaf(dy, dy, fmaf(dz, dz, dw * dw)));
}
// monotone 6-bit bin over the realistic distance range (exp 104..135)
__device__ __forceinline__ int bin6(uint key) {
    int b = (int)(key >> 22) - 208;
    return max(0, min(63, b));
}

__global__ void __launch_bounds__(256, 2) k_knn()
{
    extern __shared__ char smem_raw[];
    float4*        sc   = (float4*)smem_raw;                        // 65536
    unsigned char* hist = (unsigned char*)(smem_raw + 65536);       // 32768
    uint2*         bbuf = (uint2*)(smem_raw + 65536 + 32768);       // 12288

    int b = blockIdx.y;
    const float4* cp = (const float4*)(g_coords + b * NN * N_DIM);
    for (int i = threadIdx.x; i < NN; i += blockDim.x) sc[i] = cp[i];
    __syncthreads();

    int w    = threadIdx.x >> 5;
    int lane = threadIdx.x & 31;
    int n    = blockIdx.x * 8 + w;
    float4 q = sc[n];
    unsigned char* h8 = hist + w * 4096;      // 2 copies x 64 bins x 32 lanes
    uint* hw = (uint*)h8;
    uint lmask = (1u << lane) - 1u;

    // zero this warp's histogram (4096 B = 8 x uint4 per lane)
    {
        uint4 z = make_uint4(0, 0, 0, 0);
#pragma unroll
        for (int k = 0; k < 8; k++) ((uint4*)h8)[lane * 8 + k] = z;
    }
    __syncwarp();

    // ---- Pass A: lane-private byte histogram ----
#pragma unroll 4
    for (int t = 0; t < 128; t++) {
        int j = lane + 32 * t;
        float d = dist4(q, sc[j]);
        int bin = bin6(__float_as_uint(d));
        if (j != n)
            h8[((t & 1) << 11) + (bin << 5) + lane]++;   // own byte column
    }
    __syncwarp();

    // ---- Reduce: per-bin totals via dp4a; lane L owns bins {2L, 2L+1} ----
    int b0 = 2 * lane, b1 = 2 * lane + 1;
    unsigned c0 = 0u, c1 = 0u;
#pragma unroll
    for (int cw = 0; cw < 16; cw++) {
        unsigned off = ((cw >> 3) << 9) + (cw & 7);   // copy*512 words + word-in-row
        c0 = __dp4a(hw[off + ((unsigned)b0 << 3)], 0x01010101u, c0);
        c1 = __dp4a(hw[off + ((unsigned)b1 << 3)], 0x01010101u, c1);
    }
    int s = (int)c0 + (int)c1;
    int incl = s;
#pragma unroll
    for (int o = 1; o < 32; o <<= 1) {
        int v = __shfl_up_sync(FULL, incl, o);
        if (lane >= o) incl += v;
    }
    int excl = incl - s;

    unsigned ball = __ballot_sync(FULL, excl < KN && KN <= incl);
    int sel = __ffs(ball) - 1;
    int t0 = 0;
    if (lane == sel) t0 = (excl + (int)c0 >= KN) ? b0 : b1;
    t0 = __shfl_sync(FULL, t0, sel);

    // ---- Pass C: collect (bin<t0 accepted, ==t0 buffered) ----
    int base = (b * NN + n) * KN;
    int cbase = 0, bcnt = 0;
#pragma unroll 2
    for (int t = 0; t < 128; t++) {
        int j = lane + 32 * t;
        float d = dist4(q, sc[j]);
        uint key = __float_as_uint(d);
        int bin = bin6(key);
        bool valid = (j != n);
        bool acc = valid && bin < t0;
        bool bnd = valid && bin == t0;
        uint ba = __ballot_sync(FULL, acc);
        uint bb = __ballot_sync(FULL, bnd);
        if (acc) {
            int pos = cbase + __popc(ba & lmask);
            g_nbr_idx[base + pos] = j;
            g_nbr_w[base + pos]   = expf(-10.0f * d);
        }
        if (bnd) {
            int bp = bcnt + __popc(bb & lmask);
            if (bp < NBBUF) bbuf[w * NBBUF + bp] = make_uint2(key, (uint)j);
        }
        cbase += __popc(ba);
        bcnt  += __popc(bb);
    }
    __syncwarp();

    // ---- Boundary: exact rank among ==t0 candidates (full key, idx tiebreak) ----
    int need = KN - cbase;
    int M = min(bcnt, NBBUF);
    for (int r0 = 0; r0 < M; r0 += 32) {
        int sidx = r0 + lane;
        bool act = sidx < M;
        uint2 e = act ? bbuf[w * NBBUF + sidx] : make_uint2(0u, 0u);
        int rank = 0;
        if (act) {
            for (int i = 0; i < M; i++) {
                uint2 o = bbuf[w * NBBUF + i];   // broadcast read
                rank += (o.x < e.x) || (o.x == e.x && o.y < e.y);
            }
        }
        bool selp = act && rank < need;
        uint bs_ = __ballot_sync(FULL, selp);
        if (selp) {
            int pos = cbase + __popc(bs_ & lmask);
            g_nbr_idx[base + pos] = (int)e.y;
            g_nbr_w[base + pos]   = expf(-10.0f * __uint_as_float(e.x));
        }
        cbase += __popc(bs_);
    }
}

// ---------------------------------------------------------------------------
// K3: weighted gather -> max/mean -> concat -> @W_out + b_out.
// Warp handles 4 queries: each W_out float4 load feeds 16 FMAs.
// ---------------------------------------------------------------------------
__global__ void __launch_bounds__(256) k_agg(
    const float* __restrict__ x,
    const float* __restrict__ Wo, const float* __restrict__ bo,
    float* __restrict__ out)
{
    __shared__ float upd[32][192];
    int warp = threadIdx.x >> 5, lane = threadIdx.x & 31;
    int q0 = blockIdx.x * 32 + warp * 4;
    const float inv = 1.0f / 39.0f;

#pragma unroll
    for (int qq = 0; qq < 4; qq++) {
        int r = q0 + qq;
        const float* fb = g_features + (r >> 12) * NN * N_PROP;
        int bk = r * KN;
        float mx0 = -CUDART_INF_F, mx1 = -CUDART_INF_F, s0 = 0.f, s1 = 0.f;
#pragma unroll 8
        for (int k = 0; k < KN; k++) {
            int   jj = __ldg(&g_nbr_idx[bk + k]);
            float wt = __ldg(&g_nbr_w[bk + k]);
            float2 f = ((const float2*)(fb + jj * N_PROP))[lane];
            float v0 = wt * f.x, v1 = wt * f.y;
            mx0 = fmaxf(mx0, v0); mx1 = fmaxf(mx1, v1);
            s0 += v0; s1 += v1;
        }
        float2 xv = ((const float2*)(x + r * F_IN))[lane];
        int ql = warp * 4 + qq;
        upd[ql][2*lane]         = xv.x;
        upd[ql][2*lane + 1]     = xv.y;
        upd[ql][64 + 2*lane]    = mx0;
        upd[ql][64 + 2*lane+1]  = mx1;
        upd[ql][128 + 2*lane]   = s0 * inv;
        upd[ql][128 + 2*lane+1] = s1 * inv;
    }
    __syncwarp();

    float4 bv = ((const float4*)bo)[lane];
    float4 a0 = bv, a1 = bv, a2 = bv, a3 = bv;
    int ql0 = warp * 4;
#pragma unroll 4
    for (int c = 0; c < 192; c++) {
        float4 wv = ((const float4*)(Wo + c * N_FILT))[lane];
        float u0 = upd[ql0 + 0][c];
        float u1 = upd[ql0 + 1][c];
        float u2 = upd[ql0 + 2][c];
        float u3 = upd[ql0 + 3][c];
        a0.x = fmaf(u0, wv.x, a0.x); a0.y = fmaf(u0, wv.y, a0.y);
        a0.z = fmaf(u0, wv.z, a0.z); a0.w = fmaf(u0, wv.w, a0.w);
        a1.x = fmaf(u1, wv.x, a1.x); a1.y = fmaf(u1, wv.y, a1.y);
        a1.z = fmaf(u1, wv.z, a1.z); a1.w = fmaf(u1, wv.w, a1.w);
        a2.x = fmaf(u2, wv.x, a2.x); a2.y = fmaf(u2, wv.y, a2.y);
        a2.z = fmaf(u2, wv.z, a2.z); a2.w = fmaf(u2, wv.w, a2.w);
        a3.x = fmaf(u3, wv.x, a3.x); a3.y = fmaf(u3, wv.y, a3.y);
        a3.z = fmaf(u3, wv.z, a3.z); a3.w = fmaf(u3, wv.w, a3.w);
    }
    ((float4*)(out + (q0 + 0) * N_FILT))[lane] = a0;
    ((float4*)(out + (q0 + 1) * N_FILT))[lane] = a1;
    ((float4*)(out + (q0 + 2) * N_FILT))[lane] = a2;
    ((float4*)(out + (q0 + 3) * N_FILT))[lane] = a3;
}

// ---------------------------------------------------------------------------
extern "C" void kernel_launch(void* const* d_in, const int* in_sizes, int n_in,
                              void* d_out, int out_size)
{
    const float* x  = (const float*)d_in[0];
    const float* Wf = (const float*)d_in[1];
    const float* bf = (const float*)d_in[2];
    const float* Ws = (const float*)d_in[3];
    const float* bs = (const float*)d_in[4];
    const float* Wo = (const float*)d_in[5];
    const float* bo = (const float*)d_in[6];
    float* out = (float*)d_out;

    const int knn_smem = 65536 + 32768 + 8 * NBBUF * 8;   // 110592
    cudaFuncSetAttribute(k_knn, cudaFuncAttributeMaxDynamicSharedMemorySize, knn_smem);

    k_feat<<<BB * NN / 16, 256>>>(x, Wf, bf, Ws, bs);

    dim3 g2(NN / 8, BB);
    k_knn<<<g2, 256, knn_smem>>>();

    k_agg<<<BB * NN / 32, 256>>>(x, Wo, bo, out);
}

// round 6
// speedup vs baseline: 1.6888x; 1.2652x over previous
#include <cuda_runtime.h>
#include <math_constants.h>

// Problem constants
#define BB 4
#define NN 4096
#define F_IN 64
#define N_PROP 64
#define N_DIM 4
#define N_FILT 128
#define KN 39          // neighbors kept (top-40 minus self)
#define FULL 0xFFFFFFFFu
#define NBBUF 96
#define QPB 16         // queries per block (8 warps x 2)

// Scratch (allocation-free rule: __device__ globals)
__device__ float g_features[BB*NN*N_PROP];
__device__ float g_coords[BB*NN*N_DIM];
__device__ int   g_nbr_idx[BB*NN*KN];
__device__ float g_nbr_w[BB*NN*KN];

// ---------------------------------------------------------------------------
// K1: features = x@W_flr + b_flr ; coords = x@W_s + b_s
// ---------------------------------------------------------------------------
__global__ void __launch_bounds__(256) k_feat(
    const float* __restrict__ x,
    const float* __restrict__ Wf, const float* __restrict__ bf,
    const float* __restrict__ Ws, const float* __restrict__ bs)
{
    __shared__ float Wfs[64*64];
    __shared__ float Wss[64*4];
    __shared__ float xs[16][64];

    int t = threadIdx.x;
    int row0 = blockIdx.x * 16;

    for (int k = t; k < 64*64/4; k += 256) ((float4*)Wfs)[k] = ((const float4*)Wf)[k];
    if (t < 64) ((float4*)Wss)[t] = ((const float4*)Ws)[t];
    for (int k = t; k < 16*64/4; k += 256)
        ((float4*)xs)[k] = ((const float4*)(x + row0 * F_IN))[k];
    __syncthreads();

    int j = t & 63, rg = t >> 6;
    float b0 = bf[j];
    float a0 = b0, a1 = b0, a2 = b0, a3 = b0;
#pragma unroll
    for (int i = 0; i < 64; i++) {
        float wv = Wfs[i * 64 + j];
        a0 = fmaf(xs[rg*4+0][i], wv, a0);
        a1 = fmaf(xs[rg*4+1][i], wv, a1);
        a2 = fmaf(xs[rg*4+2][i], wv, a2);
        a3 = fmaf(xs[rg*4+3][i], wv, a3);
    }
    g_features[(row0 + rg*4 + 0) * N_PROP + j] = a0;
    g_features[(row0 + rg*4 + 1) * N_PROP + j] = a1;
    g_features[(row0 + rg*4 + 2) * N_PROP + j] = a2;
    g_features[(row0 + rg*4 + 3) * N_PROP + j] = a3;

    if (t < 64) {
        int r = t >> 2, c = t & 3;
        float a = bs[c];
#pragma unroll
        for (int i = 0; i < 64; i++)
            a = fmaf(xs[r][i], Wss[i * 4 + c], a);
        g_coords[(row0 + r) * N_DIM + c] = a;
    }
}

// ---------------------------------------------------------------------------
// K2: 2 queries per warp, exact top-39.
// Pass A: 64-bin byte histogram, rotation-indexed column (lane+t)&31 ->
//         no atomics, no same-address RMW chains, single copy.
// Reduce: dp4a column sums (self subtracted from bin 0) + warp scan -> t0.
// Pass C: collect with ballot positioning; ==t0 buffered, exact-rank fixup.
// smem: float4 sc[4096] (64K) | u8 hist[16][64][32] (32K) | uint2 bbuf[16][96] (12K)
// ---------------------------------------------------------------------------
__device__ __forceinline__ float dist4(float4 q, float4 p) {
    float dx = q.x - p.x, dy = q.y - p.y, dz = q.z - p.z, dw = q.w - p.w;
    return fmaf(dx, dx, fmaf(dy, dy, fmaf(dz, dz, dw * dw)));
}
// monotone 6-bit bin over the realistic distance range (exp 104..135)
__device__ __forceinline__ int bin6(uint key) {
    int b = (int)(key >> 22) - 208;
    return max(0, min(63, b));
}

__device__ __forceinline__ int find_t0(const uint* hw, int lane) {
    int b0 = 2 * lane, b1 = 2 * lane + 1;
    unsigned c0 = 0u, c1 = 0u;
#pragma unroll
    for (int k = 0; k < 8; k++) {
        c0 = __dp4a(hw[b0 * 8 + k], 0x01010101u, c0);
        c1 = __dp4a(hw[b1 * 8 + k], 0x01010101u, c1);
    }
    if (lane == 0) c0 -= 1u;     // self always lands in bin 0
    int s = (int)c0 + (int)c1;
    int incl = s;
#pragma unroll
    for (int o = 1; o < 32; o <<= 1) {
        int v = __shfl_up_sync(FULL, incl, o);
        if (lane >= o) incl += v;
    }
    int excl = incl - s;
    uint ball = __ballot_sync(FULL, excl < KN && KN <= incl);
    int sel = __ffs(ball) - 1;
    int t0 = 0;
    if (lane == sel) t0 = (excl + (int)c0 >= KN) ? b0 : b1;
    return __shfl_sync(FULL, t0, sel);
}

__global__ void __launch_bounds__(256, 2) k_knn()
{
    extern __shared__ char smem_raw[];
    float4*        sc   = (float4*)smem_raw;                        // 65536
    unsigned char* hist = (unsigned char*)(smem_raw + 65536);       // 32768
    uint2*         bbuf = (uint2*)(smem_raw + 65536 + 32768);       // 12288

    int b = blockIdx.y;
    const float4* cp = (const float4*)(g_coords + b * NN * N_DIM);
    for (int i = threadIdx.x; i < NN; i += blockDim.x) sc[i] = cp[i];
    __syncthreads();

    int w    = threadIdx.x >> 5;
    int lane = threadIdx.x & 31;
    int ql0  = 2 * w, ql1 = 2 * w + 1;       // block-local query ids
    int n0   = blockIdx.x * QPB + ql0;
    int n1   = n0 + 1;
    float4 q0 = sc[n0];
    float4 q1 = sc[n1];
    unsigned char* h0 = hist + ql0 * 2048;
    unsigned char* h1 = hist + ql1 * 2048;
    uint lmask = (1u << lane) - 1u;

    // zero this warp's two histograms (4096 B total = 8 x uint4 per lane)
    {
        uint4 z = make_uint4(0, 0, 0, 0);
#pragma unroll
        for (int k = 0; k < 8; k++) ((uint4*)h0)[lane * 8 + k] = z;
    }
    __syncwarp();

    // ---- Pass A: byte histogram, rotated column kills RMW chains ----
#pragma unroll 4
    for (int t = 0; t < 128; t++) {
        int j = lane + 32 * t;
        float4 p = sc[j];
        float d0 = dist4(q0, p);
        float d1 = dist4(q1, p);
        int col = (lane + t) & 31;
        h0[(bin6(__float_as_uint(d0)) << 5) + col]++;
        h1[(bin6(__float_as_uint(d1)) << 5) + col]++;
    }
    __syncwarp();

    // ---- Reduce: boundary bins for both queries ----
    int t0a = find_t0((const uint*)h0, lane);
    int t0b = find_t0((const uint*)h1, lane);

    // ---- Pass C: collect (bin<t0 accepted, ==t0 buffered) ----
    int base0 = (b * NN + n0) * KN;
    int base1 = (b * NN + n1) * KN;
    int ca = 0, ba_ = 0;     // q0: accepted, boundary counts
    int cb = 0, bb_ = 0;     // q1
#pragma unroll 2
    for (int t = 0; t < 128; t++) {
        int j = lane + 32 * t;
        float4 p = sc[j];

        float d0 = dist4(q0, p);
        uint k0 = __float_as_uint(d0);
        int bn0 = bin6(k0);
        bool v0 = (j != n0);
        bool ac0 = v0 && bn0 < t0a;
        bool bd0 = v0 && bn0 == t0a;
        uint A0 = __ballot_sync(FULL, ac0);
        uint B0 = __ballot_sync(FULL, bd0);
        if (ac0) {
            int pos = ca + __popc(A0 & lmask);
            g_nbr_idx[base0 + pos] = j;
            g_nbr_w[base0 + pos]   = __expf(-10.0f * d0);
        }
        if (bd0) {
            int bp = ba_ + __popc(B0 & lmask);
            if (bp < NBBUF) bbuf[ql0 * NBBUF + bp] = make_uint2(k0, (uint)j);
        }
        ca  += __popc(A0);
        ba_ += __popc(B0);

        float d1 = dist4(q1, p);
        uint k1 = __float_as_uint(d1);
        int bn1 = bin6(k1);
        bool v1 = (j != n1);
        bool ac1 = v1 && bn1 < t0b;
        bool bd1 = v1 && bn1 == t0b;
        uint A1 = __ballot_sync(FULL, ac1);
        uint B1 = __ballot_sync(FULL, bd1);
        if (ac1) {
            int pos = cb + __popc(A1 & lmask);
            g_nbr_idx[base1 + pos] = j;
            g_nbr_w[base1 + pos]   = __expf(-10.0f * d1);
        }
        if (bd1) {
            int bp = bb_ + __popc(B1 & lmask);
            if (bp < NBBUF) bbuf[ql1 * NBBUF + bp] = make_uint2(k1, (uint)j);
        }
        cb  += __popc(A1);
        bb_ += __popc(B1);
    }
    __syncwarp();

    // ---- Boundary: exact rank among ==t0 candidates, per query ----
#pragma unroll
    for (int qq = 0; qq < 2; qq++) {
        int ql   = (qq == 0) ? ql0 : ql1;
        int need = KN - ((qq == 0) ? ca : cb);
        int M    = min((qq == 0) ? ba_ : bb_, NBBUF);
        int cpos = (qq == 0) ? ca : cb;
        int bse  = (qq == 0) ? base0 : base1;
        for (int r0 = 0; r0 < M; r0 += 32) {
            int sidx = r0 + lane;
            bool act = sidx < M;
            uint2 e = act ? bbuf[ql * NBBUF + sidx] : make_uint2(0u, 0u);
            int rank = 0;
            if (act) {
                for (int i = 0; i < M; i++) {
                    uint2 o = bbuf[ql * NBBUF + i];   // broadcast read
                    rank += (o.x < e.x) || (o.x == e.x && o.y < e.y);
                }
            }
            bool selp = act && rank < need;
            uint bs_ = __ballot_sync(FULL, selp);
            if (selp) {
                int pos = cpos + __popc(bs_ & lmask);
                g_nbr_idx[bse + pos] = (int)e.y;
                g_nbr_w[bse + pos]   = __expf(-10.0f * __uint_as_float(e.x));
            }
            cpos += __popc(bs_);
        }
    }
}

// ---------------------------------------------------------------------------
// K3: weighted gather -> max/mean -> concat -> @W_out + b_out.
// Warp handles 4 queries: each W_out float4 load feeds 16 FMAs.
// ---------------------------------------------------------------------------
__global__ void __launch_bounds__(256) k_agg(
    const float* __restrict__ x,
    const float* __restrict__ Wo, const float* __restrict__ bo,
    float* __restrict__ out)
{
    __shared__ float upd[32][192];
    int warp = threadIdx.x >> 5, lane = threadIdx.x & 31;
    int q0 = blockIdx.x * 32 + warp * 4;
    const float inv = 1.0f / 39.0f;

#pragma unroll
    for (int qq = 0; qq < 4; qq++) {
        int r = q0 + qq;
        const float* fb = g_features + (r >> 12) * NN * N_PROP;
        int bk = r * KN;
        float mx0 = -CUDART_INF_F, mx1 = -CUDART_INF_F, s0 = 0.f, s1 = 0.f;
#pragma unroll 8
        for (int k = 0; k < KN; k++) {
            int   jj = __ldg(&g_nbr_idx[bk + k]);
            float wt = __ldg(&g_nbr_w[bk + k]);
            float2 f = ((const float2*)(fb + jj * N_PROP))[lane];
            float v0 = wt * f.x, v1 = wt * f.y;
            mx0 = fmaxf(mx0, v0); mx1 = fmaxf(mx1, v1);
            s0 += v0; s1 += v1;
        }
        float2 xv = ((const float2*)(x + r * F_IN))[lane];
        int ql = warp * 4 + qq;
        upd[ql][2*lane]         = xv.x;
        upd[ql][2*lane + 1]     = xv.y;
        upd[ql][64 + 2*lane]    = mx0;
        upd[ql][64 + 2*lane+1]  = mx1;
        upd[ql][128 + 2*lane]   = s0 * inv;
        upd[ql][128 + 2*lane+1] = s1 * inv;
    }
    __syncwarp();

    float4 bv = ((const float4*)bo)[lane];
    float4 a0 = bv, a1 = bv, a2 = bv, a3 = bv;
    int ql0 = warp * 4;
#pragma unroll 4
    for (int c = 0; c < 192; c++) {
        float4 wv = ((const float4*)(Wo + c * N_FILT))[lane];
        float u0 = upd[ql0 + 0][c];
        float u1 = upd[ql0 + 1][c];
        float u2 = upd[ql0 + 2][c];
        float u3 = upd[ql0 + 3][c];
        a0.x = fmaf(u0, wv.x, a0.x); a0.y = fmaf(u0, wv.y, a0.y);
        a0.z = fmaf(u0, wv.z, a0.z); a0.w = fmaf(u0, wv.w, a0.w);
        a1.x = fmaf(u1, wv.x, a1.x); a1.y = fmaf(u1, wv.y, a1.y);
        a1.z = fmaf(u1, wv.z, a1.z); a1.w = fmaf(u1, wv.w, a1.w);
        a2.x = fmaf(u2, wv.x, a2.x); a2.y = fmaf(u2, wv.y, a2.y);
        a2.z = fmaf(u2, wv.z, a2.z); a2.w = fmaf(u2, wv.w, a2.w);
        a3.x = fmaf(u3, wv.x, a3.x); a3.y = fmaf(u3, wv.y, a3.y);
        a3.z = fmaf(u3, wv.z, a3.z); a3.w = fmaf(u3, wv.w, a3.w);
    }
    ((float4*)(out + (q0 + 0) * N_FILT))[lane] = a0;
    ((float4*)(out + (q0 + 1) * N_FILT))[lane] = a1;
    ((float4*)(out + (q0 + 2) * N_FILT))[lane] = a2;
    ((float4*)(out + (q0 + 3) * N_FILT))[lane] = a3;
}

// ---------------------------------------------------------------------------
extern "C" void kernel_launch(void* const* d_in, const int* in_sizes, int n_in,
                              void* d_out, int out_size)
{
    const float* x  = (const float*)d_in[0];
    const float* Wf = (const float*)d_in[1];
    const float* bf = (const float*)d_in[2];
    const float* Ws = (const float*)d_in[3];
    const float* bs = (const float*)d_in[4];
    const float* Wo = (const float*)d_in[5];
    const float* bo = (const float*)d_in[6];
    float* out = (float*)d_out;

    const int knn_smem = 65536 + 32768 + QPB * NBBUF * 8;   // 110592
    cudaFuncSetAttribute(k_knn, cudaFuncAttributeMaxDynamicSharedMemorySize, knn_smem);

    k_feat<<<BB * NN / 16, 256>>>(x, Wf, bf, Ws, bs);

    dim3 g2(NN / QPB, BB);
    k_knn<<<g2, 256, knn_smem>>>();

    k_agg<<<BB * NN / 32, 256>>>(x, Wo, bo, out);
}